// round 5
// baseline (speedup 1.0000x reference)
#include <cuda_runtime.h>
#include <math.h>

#define SEQ 20
#define H   128
#define NC  100000

typedef unsigned long long u64;

// ---------------- device scratch (no allocations allowed) ----------------
__device__ float g_xg[2][SEQ][4 * H];    // fwd/bwd gate pre-activations from x (+both biases)
__device__ float g_hseq[2][SEQ][H];      // fwd/bwd hidden outputs (bwd kept in scan order)
__device__ float g_xgl[SEQ][8 * H];      // combined-LSTM gate pre-activations from comb input
__device__ float g_hl[SEQ][2 * H];       // combined-LSTM hidden outputs
__device__ int   g_rl;                   // combined recurrence sync counter

// ---------------- f32x2 helpers ----------------
__device__ __forceinline__ u64 pk(float a, float b) {
    u64 r; asm("mov.b64 %0, {%1, %2};" : "=l"(r) : "f"(a), "f"(b)); return r;
}
__device__ __forceinline__ u64 fma2(u64 a, u64 b, u64 c) {
    u64 d; asm("fma.rn.f32x2 %0, %1, %2, %3;" : "=l"(d) : "l"(a), "l"(b), "l"(c)); return d;
}
__device__ __forceinline__ float2 unpk(u64 v) {
    float a, b; asm("mov.b64 {%0, %1}, %2;" : "=f"(a), "=f"(b) : "l"(v));
    return make_float2(a, b);
}
__device__ __forceinline__ float sigf(float x) { return 1.0f / (1.0f + expf(-x)); }

// =====================================================================
// K0: x-projections for fwd/bwd LSTMs + reset sync counter.
// grid = 40 blocks (dir*20+t), 512 threads (one gate row each).
// =====================================================================
__global__ void k_pre(const float* __restrict__ x,
                      const float* __restrict__ Wih_f, const float* __restrict__ bih_f,
                      const float* __restrict__ bhh_f,
                      const float* __restrict__ Wih_b, const float* __restrict__ bih_b,
                      const float* __restrict__ bhh_b)
{
    int bx  = blockIdx.x;
    int dir = bx / SEQ;
    int t   = bx % SEQ;
    int r   = threadIdx.x;              // 0..511 gate row

    __shared__ float4 xs[H / 4];
    if (r < H / 4)
        xs[r] = ((const float4*)(x + (dir ? (SEQ - 1 - t) : t) * H))[r];
    if (bx == 0 && r == 0) g_rl = 0;    // reset combined-recurrence counter each replay
    __syncthreads();

    const float* Wih = dir ? Wih_b : Wih_f;
    const float4* wr = (const float4*)(Wih + r * H);
    float acc = 0.f;
#pragma unroll
    for (int i = 0; i < H / 4; i++) {
        float4 w = __ldg(&wr[i]);
        float4 xv = xs[i];
        acc += w.x * xv.x + w.y * xv.y + w.z * xv.z + w.w * xv.w;
    }
    const float* bi = dir ? bih_b : bih_f;
    const float* bh = dir ? bhh_b : bhh_f;
    g_xg[dir][t][r] = acc + bi[r] + bh[r];
}

// =====================================================================
// K1: fwd + bwd recurrences. One block per direction, no inter-block sync.
// 512 threads, one gate row each. Whh row: cols 0..63 in registers (f32x2),
// cols 64..127 in 128KB shared (row-minor -> conflict-free).
// x-gate pre-activations for all 20 steps staged into smem at entry so the
// per-step critical path reads LDS (~29cyc) instead of L2 (~240cyc).
// =====================================================================
#define FB_WSH_BYTES (16 * 512 * 16)
#define FB_XG_BYTES  (SEQ * 512 * 4)
#define FB_SMEM (FB_WSH_BYTES + FB_XG_BYTES + 64 * 8 + 512 * 4 + 128 * 4)

__global__ void __launch_bounds__(512)
k_fb(const float* __restrict__ Whh_f, const float* __restrict__ Whh_b,
     const float* __restrict__ h0f, const float* __restrict__ c0f,
     const float* __restrict__ h0b, const float* __restrict__ c0b)
{
    extern __shared__ __align__(16) char smem[];
    ulonglong2* wsh  = (ulonglong2*)smem;                          // [16][512] (cols 64..127)
    float*      xgsh = (float*)(smem + FB_WSH_BYTES);              // [SEQ][512]
    u64*        hsh  = (u64*)(smem + FB_WSH_BYTES + FB_XG_BYTES);  // [64] packed h pairs
    float*      gates = (float*)(smem + FB_WSH_BYTES + FB_XG_BYTES + 64 * 8);  // [512]
    float*      csh  = gates + 512;                                // [128]

    int dir = blockIdx.x;
    int r   = threadIdx.x;
    const float* Whh = dir ? Whh_b : Whh_f;
    const float* h0  = dir ? h0b : h0f;
    const float* c0  = dir ? c0b : c0f;

    const float4* wr = (const float4*)(Whh + r * H);
    u64 wreg[32];
#pragma unroll
    for (int i = 0; i < 16; i++) {                 // cols 0..63 -> registers
        float4 w = __ldg(&wr[i]);
        wreg[2 * i]     = pk(w.x, w.y);
        wreg[2 * i + 1] = pk(w.z, w.w);
    }
#pragma unroll
    for (int m = 0; m < 16; m++) {                 // cols 64..127 -> shared
        float4 w = __ldg(&wr[16 + m]);
        wsh[m * 512 + r] = make_ulonglong2(pk(w.x, w.y), pk(w.z, w.w));
    }
#pragma unroll
    for (int t = 0; t < SEQ; t++)                  // stage x-gates (coalesced, parallel)
        xgsh[t * 512 + r] = g_xg[dir][t][r];
    if (r < 64) hsh[r] = pk(h0[2 * r], h0[2 * r + 1]);
    if (r < H)  csh[r] = c0[r];
    __syncthreads();

    const ulonglong2* h2p = (const ulonglong2*)hsh;
    for (int t = 0; t < SEQ; t++) {
        u64 acc0 = 0ull, acc1 = 0ull;
#pragma unroll
        for (int m = 0; m < 16; m++) {             // register-resident half
            ulonglong2 hv = h2p[m];
            acc0 = fma2(wreg[2 * m],     hv.x, acc0);
            acc1 = fma2(wreg[2 * m + 1], hv.y, acc1);
        }
#pragma unroll
        for (int m = 0; m < 16; m++) {             // shared half
            ulonglong2 hv = h2p[16 + m];
            ulonglong2 wv = wsh[m * 512 + r];
            acc0 = fma2(wv.x, hv.x, acc0);
            acc1 = fma2(wv.y, hv.y, acc1);
        }
        float2 a = unpk(acc0), b = unpk(acc1);
        gates[r] = a.x + a.y + b.x + b.y + xgsh[t * 512 + r];
        __syncthreads();
        if (r < H) {
            float gi = gates[r],         gf = gates[H + r];
            float gg = gates[2 * H + r], go = gates[3 * H + r];
            float c2 = sigf(gf) * csh[r] + sigf(gi) * tanhf(gg);
            float h2 = sigf(go) * tanhf(c2);
            csh[r] = c2;
            ((float*)hsh)[r] = h2;
            g_hseq[dir][t][r] = h2;
        }
        __syncthreads();
    }
}

// =====================================================================
// K2: combined-LSTM input projections: Wih_l @ concat(fwd,bwd) + biases.
// grid = (20 t) x (4 row-chunks), 256 threads (one of 1024 gate rows each).
// =====================================================================
__global__ void k_lpre(const float* __restrict__ Wih_l,
                       const float* __restrict__ bih_l, const float* __restrict__ bhh_l)
{
    int t     = blockIdx.x >> 2;
    int chunk = blockIdx.x & 3;
    int tid   = threadIdx.x;            // 0..255
    int row   = chunk * 256 + tid;

    __shared__ float cs[2 * H];
    if (tid < H) cs[tid] = g_hseq[0][t][tid];
    else         cs[tid] = g_hseq[1][t][tid - H];
    __syncthreads();

    const float4* wr = (const float4*)(Wih_l + row * 2 * H);
    const float4* cv = (const float4*)cs;
    float acc = 0.f;
#pragma unroll
    for (int i = 0; i < 64; i++) {
        float4 w = __ldg(&wr[i]);
        float4 h = cv[i];
        acc += w.x * h.x + w.y * h.y + w.z * h.z + w.w * h.w;
    }
    g_xgl[t][row] = acc + bih_l[row] + bhh_l[row];
}

// =====================================================================
// K3: combined recurrence (2H=256 cells, Whh_l = 1MB). 8 persistent blocks,
// 32 cells each; weights register-resident (64 floats/thread as f32x2);
// per-step cross-block release/acquire sync via global counter.
// x-gate pre-activations staged to smem (pre-gathered through grow map).
// =====================================================================
__global__ void __launch_bounds__(512)
k_l(const float* __restrict__ Whh_l,
    const float* __restrict__ h0l, const float* __restrict__ c0l)
{
    const int NB = 8, CPB = 32;
    int cb   = blockIdx.x * CPB;
    int tid  = threadIdx.x;
    int lr   = tid >> 2;                 // local row 0..127
    int seg  = tid & 3;                  // k-quarter
    int gate = lr >> 5;                  // 0..3 (i,f,g,o)
    int cell = cb + (lr & 31);
    int grow = gate * 256 + cell;        // global gate row in [0,1024)

    __shared__ float gates[128];
    __shared__ float csh[CPB];
    __shared__ float xgl_sh[SEQ][128];   // staged x-gates, indexed by local row

    const float4* wr = (const float4*)(Whh_l + grow * 256 + seg * 64);
    u64 wreg[32];
#pragma unroll
    for (int i = 0; i < 16; i++) {
        float4 w = __ldg(&wr[i]);
        wreg[2 * i]     = pk(w.x, w.y);
        wreg[2 * i + 1] = pk(w.z, w.w);
    }
    // stage x-gates: xgl_sh[t][l] = g_xgl[t][grow(l)]
    for (int idx = tid; idx < SEQ * 128; idx += 512) {
        int t = idx >> 7, l = idx & 127;
        int gl = (l >> 5) * 256 + cb + (l & 31);
        xgl_sh[t][l] = g_xgl[t][gl];
    }
    if (tid < CPB) csh[tid] = c0l[cb + tid];
    __syncthreads();

    for (int t = 0; t < SEQ; t++) {
        if (t > 0) {
            if (tid == 0) {
                // plain L2 poll (no atomic-ALU serialization against producers)
                while (*((volatile int*)&g_rl) < NB * t) { }
                __threadfence();         // acquire: order dependent loads after observed counter
            }
            __syncthreads();
        }
        const float* hprev = t ? g_hl[t - 1] : h0l;
        const float4* hp4  = (const float4*)(hprev + seg * 64);
        u64 acc0 = 0ull, acc1 = 0ull;
#pragma unroll
        for (int i = 0; i < 16; i++) {
            float4 h4 = __ldcg(&hp4[i]);     // bypass L1: cross-block producer data
            acc0 = fma2(wreg[2 * i],     pk(h4.x, h4.y), acc0);
            acc1 = fma2(wreg[2 * i + 1], pk(h4.z, h4.w), acc1);
        }
        float2 a = unpk(acc0), b = unpk(acc1);
        float s = a.x + a.y + b.x + b.y;
        s += __shfl_xor_sync(0xFFFFFFFFu, s, 1);
        s += __shfl_xor_sync(0xFFFFFFFFu, s, 2);
        if (seg == 0) gates[lr] = s + xgl_sh[t][lr];
        __syncthreads();
        if (tid < CPB) {
            float gi = gates[tid],           gf = gates[CPB + tid];
            float gg = gates[2 * CPB + tid], go = gates[3 * CPB + tid];
            float c2 = sigf(gf) * csh[tid] + sigf(gi) * tanhf(gg);
            float h2 = sigf(go) * tanhf(c2);
            csh[tid] = c2;
            g_hl[t][cb + tid] = h2;
        }
        __threadfence();                 // release: h stores visible before counter bump
        __syncthreads();
        if (tid == 0) atomicAdd(&g_rl, 1);
    }
}

// =====================================================================
// K4: out[t][n] = hl[t] . Wlin[n] + blin[n]   (20 x 100000)
// Memory-bound on Wlin (102MB, read once). f32x2 over t-pairs.
// Lane map: rr=lane%4 (row), ks=lane/4 (k-eighth) -> every LDG.128 covers
// 4 full 128B lines. 2 rows/thread, 8 warps x 8 rows = 64 rows/block.
// Software-pipelined: iteration c+1's weight loads issue before c's FMAs.
// =====================================================================
__global__ void __launch_bounds__(256)
k_gemm(const float* __restrict__ Wlin, const float* __restrict__ blin,
       float* __restrict__ out)
{
    __shared__ __align__(16) float2 fbp[10][256];   // fbp[tp][k] = (hl[2tp][k], hl[2tp+1][k])
    int tid = threadIdx.x;
#pragma unroll
    for (int i = 0; i < 10; i++) {
        int idx = i * 256 + tid;
        int tp = idx >> 8, k = idx & 255;
        fbp[tp][k] = make_float2(g_hl[2 * tp][k], g_hl[2 * tp + 1][k]);
    }
    __syncthreads();

    int warp = tid >> 5, lane = tid & 31;
    int rr = lane & 3, ks = lane >> 2;
    int rbase = blockIdx.x * 64 + warp * 8 + rr;
    int r0c = (rbase < NC)     ? rbase     : NC - 1;
    int r1c = (rbase + 4 < NC) ? rbase + 4 : NC - 1;
    const float4* wp0 = (const float4*)(Wlin + (size_t)r0c * 256 + ks * 4);
    const float4* wp1 = (const float4*)(Wlin + (size_t)r1c * 256 + ks * 4);

    u64 acc[2][10];
#pragma unroll
    for (int g = 0; g < 2; g++)
#pragma unroll
        for (int tp = 0; tp < 10; tp++) acc[g][tp] = 0ull;

    float4 wc[2], wn[2];
    wc[0] = __ldg(wp0); wc[1] = __ldg(wp1);
    wn[0] = wc[0];      wn[1] = wc[1];

#pragma unroll
    for (int c = 0; c < 8; c++) {
        if (c < 7) {                       // prefetch next k-chunk (overlaps FMAs below)
            wn[0] = __ldg(wp0 + (c + 1) * 8);
            wn[1] = __ldg(wp1 + (c + 1) * 8);
        }
        int k0 = c * 32 + ks * 4;
        u64 ws[2][4];
#pragma unroll
        for (int g = 0; g < 2; g++) {
            ws[g][0] = pk(wc[g].x, wc[g].x); ws[g][1] = pk(wc[g].y, wc[g].y);
            ws[g][2] = pk(wc[g].z, wc[g].z); ws[g][3] = pk(wc[g].w, wc[g].w);
        }
#pragma unroll
        for (int tp = 0; tp < 10; tp++) {
            ulonglong2 f01 = *(const ulonglong2*)&fbp[tp][k0];
            ulonglong2 f23 = *(const ulonglong2*)&fbp[tp][k0 + 2];
#pragma unroll
            for (int g = 0; g < 2; g++) {
                acc[g][tp] = fma2(ws[g][0], f01.x, acc[g][tp]);
                acc[g][tp] = fma2(ws[g][1], f01.y, acc[g][tp]);
                acc[g][tp] = fma2(ws[g][2], f23.x, acc[g][tp]);
                acc[g][tp] = fma2(ws[g][3], f23.y, acc[g][tp]);
            }
        }
        wc[0] = wn[0]; wc[1] = wn[1];
    }

    // reduce across the 8 k-eighth lanes (xor 4,8,16), then write
#pragma unroll
    for (int g = 0; g < 2; g++) {
        int r = rbase + g * 4;
        float bv = (r < NC) ? __ldg(&blin[r]) : 0.f;
#pragma unroll
        for (int tp = 0; tp < 10; tp++) {
            float2 v = unpk(acc[g][tp]);
#pragma unroll
            for (int off = 4; off <= 16; off <<= 1) {
                v.x += __shfl_xor_sync(0xFFFFFFFFu, v.x, off);
                v.y += __shfl_xor_sync(0xFFFFFFFFu, v.y, off);
            }
            if (ks == 0 && r < NC) {
                out[(size_t)(2 * tp) * NC + r]     = v.x + bv;
                out[(size_t)(2 * tp + 1) * NC + r] = v.y + bv;
            }
        }
    }
}

// =====================================================================
extern "C" void kernel_launch(void* const* d_in, const int* in_sizes, int n_in,
                              void* d_out, int out_size)
{
    const float* x     = (const float*)d_in[0];
    const float* h0f   = (const float*)d_in[1];
    const float* c0f   = (const float*)d_in[2];
    const float* h0b   = (const float*)d_in[3];
    const float* c0b   = (const float*)d_in[4];
    const float* h0l   = (const float*)d_in[5];
    const float* c0l   = (const float*)d_in[6];
    const float* Wih_f = (const float*)d_in[7];
    const float* Whh_f = (const float*)d_in[8];
    const float* bih_f = (const float*)d_in[9];
    const float* bhh_f = (const float*)d_in[10];
    const float* Wih_b = (const float*)d_in[11];
    const float* Whh_b = (const float*)d_in[12];
    const float* bih_b = (const float*)d_in[13];
    const float* bhh_b = (const float*)d_in[14];
    const float* Wih_l = (const float*)d_in[15];
    const float* Whh_l = (const float*)d_in[16];
    const float* bih_l = (const float*)d_in[17];
    const float* bhh_l = (const float*)d_in[18];
    const float* Wlin  = (const float*)d_in[19];
    const float* blin  = (const float*)d_in[20];
    float* out = (float*)d_out;

    cudaFuncSetAttribute(k_fb, cudaFuncAttributeMaxDynamicSharedMemorySize, FB_SMEM);

    k_pre<<<2 * SEQ, 512>>>(x, Wih_f, bih_f, bhh_f, Wih_b, bih_b, bhh_b);
    k_fb<<<2, 512, FB_SMEM>>>(Whh_f, Whh_b, h0f, c0f, h0b, c0b);
    k_lpre<<<SEQ * 4, 256>>>(Wih_l, bih_l, bhh_l);
    k_l<<<8, 512>>>(Whh_l, h0l, c0l);
    k_gemm<<<(NC + 63) / 64, 256>>>(Wlin, blin, out);
}

// round 7
// speedup vs baseline: 1.1380x; 1.1380x over previous
#include <cuda_runtime.h>
#include <math.h>
#include <stdint.h>

#define SEQ 20
#define H   128
#define NC  100000

typedef unsigned long long u64;

// ---------------- device scratch (no allocations allowed) ----------------
__device__ float g_xg[2][SEQ][4 * H];    // fwd/bwd gate pre-activations from x (+both biases)
__device__ float g_hseq[2][SEQ][H];      // fwd/bwd hidden outputs (bwd kept in scan order)
__device__ float g_xgl[SEQ][8 * H];      // combined-LSTM gate pre-activations from comb input
__device__ float g_hl[SEQ][2 * H];       // combined-LSTM hidden outputs
__device__ float g_sink[144 * 16];       // prefetch DCE-prevention sink

// ---------------- f32x2 helpers ----------------
__device__ __forceinline__ u64 pk(float a, float b) {
    u64 r; asm("mov.b64 %0, {%1, %2};" : "=l"(r) : "f"(a), "f"(b)); return r;
}
__device__ __forceinline__ u64 fma2(u64 a, u64 b, u64 c) {
    u64 d; asm("fma.rn.f32x2 %0, %1, %2, %3;" : "=l"(d) : "l"(a), "l"(b), "l"(c)); return d;
}
__device__ __forceinline__ float2 unpk(u64 v) {
    float a, b; asm("mov.b64 {%0, %1}, %2;" : "=f"(a), "=f"(b) : "l"(v));
    return make_float2(a, b);
}
// fast activations: MUFU-based, err ~1e-6 (tolerance is 1e-3)
__device__ __forceinline__ float sigf(float x) {
    return __fdividef(1.0f, 1.0f + __expf(-x));
}
__device__ __forceinline__ float tanhfast(float x) {
    float e = __expf(-2.0f * fabsf(x));            // in (0,1]; no overflow
    float r = __fdividef(1.0f - e, 1.0f + e);
    return copysignf(r, x);
}

__device__ __forceinline__ uint32_t smem_u32(const void* p) {
    uint32_t a;
    asm("{ .reg .u64 t; cvta.to.shared.u64 t, %1; cvt.u32.u64 %0, t; }" : "=r"(a) : "l"(p));
    return a;
}

// =====================================================================
// K0: x-projections for fwd/bwd LSTMs.
// grid = 40 blocks (dir*20+t), 512 threads (one gate row each).
// =====================================================================
__global__ void k_pre(const float* __restrict__ x,
                      const float* __restrict__ Wih_f, const float* __restrict__ bih_f,
                      const float* __restrict__ bhh_f,
                      const float* __restrict__ Wih_b, const float* __restrict__ bih_b,
                      const float* __restrict__ bhh_b)
{
    int bx  = blockIdx.x;
    int dir = bx / SEQ;
    int t   = bx % SEQ;
    int r   = threadIdx.x;              // 0..511 gate row

    __shared__ float4 xs[H / 4];
    if (r < H / 4)
        xs[r] = ((const float4*)(x + (dir ? (SEQ - 1 - t) : t) * H))[r];
    __syncthreads();

    const float* Wih = dir ? Wih_b : Wih_f;
    const float4* wr = (const float4*)(Wih + r * H);
    float acc = 0.f;
#pragma unroll
    for (int i = 0; i < H / 4; i++) {
        float4 w = __ldg(&wr[i]);
        float4 xv = xs[i];
        acc += w.x * xv.x + w.y * xv.y + w.z * xv.z + w.w * xv.w;
    }
    const float* bi = dir ? bih_b : bih_f;
    const float* bh = dir ? bhh_b : bhh_f;
    g_xg[dir][t][r] = acc + bi[r] + bh[r];
}

// =====================================================================
// K1: fwd + bwd recurrences. One block per direction, no inter-block sync.
// 512 threads, one gate row each. Whh row: cols 0..63 in registers (f32x2),
// cols 64..127 in 128KB shared (row-minor -> conflict-free).
// x-gate pre-activations for all 20 steps staged into smem at entry.
// =====================================================================
#define FB_WSH_BYTES (16 * 512 * 16)
#define FB_XG_BYTES  (SEQ * 512 * 4)
#define FB_SMEM (FB_WSH_BYTES + FB_XG_BYTES + 64 * 8 + 512 * 4 + 128 * 4)

__global__ void __launch_bounds__(512)
k_fb(const float* __restrict__ Whh_f, const float* __restrict__ Whh_b,
     const float* __restrict__ h0f, const float* __restrict__ c0f,
     const float* __restrict__ h0b, const float* __restrict__ c0b)
{
    extern __shared__ __align__(16) char smem[];
    ulonglong2* wsh  = (ulonglong2*)smem;                          // [16][512] (cols 64..127)
    float*      xgsh = (float*)(smem + FB_WSH_BYTES);              // [SEQ][512]
    u64*        hsh  = (u64*)(smem + FB_WSH_BYTES + FB_XG_BYTES);  // [64] packed h pairs
    float*      gates = (float*)(smem + FB_WSH_BYTES + FB_XG_BYTES + 64 * 8);  // [512]
    float*      csh  = gates + 512;                                // [128]

    int dir = blockIdx.x;
    int r   = threadIdx.x;
    const float* Whh = dir ? Whh_b : Whh_f;
    const float* h0  = dir ? h0b : h0f;
    const float* c0  = dir ? c0b : c0f;

    const float4* wr = (const float4*)(Whh + r * H);
    u64 wreg[32];
#pragma unroll
    for (int i = 0; i < 16; i++) {                 // cols 0..63 -> registers
        float4 w = __ldg(&wr[i]);
        wreg[2 * i]     = pk(w.x, w.y);
        wreg[2 * i + 1] = pk(w.z, w.w);
    }
#pragma unroll
    for (int m = 0; m < 16; m++) {                 // cols 64..127 -> shared
        float4 w = __ldg(&wr[16 + m]);
        wsh[m * 512 + r] = make_ulonglong2(pk(w.x, w.y), pk(w.z, w.w));
    }
#pragma unroll
    for (int t = 0; t < SEQ; t++)                  // stage x-gates (coalesced, parallel)
        xgsh[t * 512 + r] = g_xg[dir][t][r];
    if (r < 64) hsh[r] = pk(h0[2 * r], h0[2 * r + 1]);
    if (r < H)  csh[r] = c0[r];
    __syncthreads();

    const ulonglong2* h2p = (const ulonglong2*)hsh;
    for (int t = 0; t < SEQ; t++) {
        u64 acc0 = 0ull, acc1 = 0ull;
#pragma unroll
        for (int m = 0; m < 16; m++) {             // register-resident half
            ulonglong2 hv = h2p[m];
            acc0 = fma2(wreg[2 * m],     hv.x, acc0);
            acc1 = fma2(wreg[2 * m + 1], hv.y, acc1);
        }
#pragma unroll
        for (int m = 0; m < 16; m++) {             // shared half
            ulonglong2 hv = h2p[16 + m];
            ulonglong2 wv = wsh[m * 512 + r];
            acc0 = fma2(wv.x, hv.x, acc0);
            acc1 = fma2(wv.y, hv.y, acc1);
        }
        float2 a = unpk(acc0), b = unpk(acc1);
        gates[r] = a.x + a.y + b.x + b.y + xgsh[t * 512 + r];
        __syncthreads();
        if (r < H) {
            float gi = gates[r],         gf = gates[H + r];
            float gg = gates[2 * H + r], go = gates[3 * H + r];
            float c2 = sigf(gf) * csh[r] + sigf(gi) * tanhfast(gg);
            float h2 = sigf(go) * tanhfast(c2);
            csh[r] = c2;
            ((float*)hsh)[r] = h2;
            g_hseq[dir][t][r] = h2;
        }
        __syncthreads();
    }
}

// =====================================================================
// K2: combined-LSTM input projections: Wih_l @ concat(fwd,bwd) + biases.
// grid = (20 t) x (4 row-chunks), 256 threads (one of 1024 gate rows each).
// =====================================================================
__global__ void k_lpre(const float* __restrict__ Wih_l,
                       const float* __restrict__ bih_l, const float* __restrict__ bhh_l)
{
    int t     = blockIdx.x >> 2;
    int chunk = blockIdx.x & 3;
    int tid   = threadIdx.x;            // 0..255
    int row   = chunk * 256 + tid;

    __shared__ float cs[2 * H];
    if (tid < H) cs[tid] = g_hseq[0][t][tid];
    else         cs[tid] = g_hseq[1][t][tid - H];
    __syncthreads();

    const float4* wr = (const float4*)(Wih_l + row * 2 * H);
    const float4* cv = (const float4*)cs;
    float acc = 0.f;
#pragma unroll
    for (int i = 0; i < 64; i++) {
        float4 w = __ldg(&wr[i]);
        float4 h = cv[i];
        acc += w.x * h.x + w.y * h.y + w.z * h.z + w.w * h.w;
    }
    g_xgl[t][row] = acc + bih_l[row] + bhh_l[row];
}

// =====================================================================
// K3: combined recurrence (2H=256 cells, Whh_l = 1MB) + Wlin L2 prewarm.
// grid = 144 = 18 clusters of 8. Cluster 0 (blocks 0..7) runs the
// recurrence: 32 cells/CTA, weights register-resident, h vector in
// per-CTA smem (double-buffered), broadcast via st.shared::cluster,
// per-step sync = barrier.cluster (release/acquire built in).
// Blocks 8..143 stream Wlin through L2 (126MB L2 holds the 102MB) so the
// later k_gemm hits L2 instead of DRAM. Prefetch is fully concurrent
// with the recurrence (separate SMs) -> zero serial-chain cost.
// =====================================================================
__global__ void __launch_bounds__(512) __cluster_dims__(8, 1, 1)
k_l(const float* __restrict__ Whh_l,
    const float* __restrict__ h0l, const float* __restrict__ c0l,
    const float* __restrict__ Wlin)
{
    const int CPB = 32;
    int tid  = threadIdx.x;

    if (blockIdx.x >= 8) {
        // ---- Wlin L2 prewarm (136 blocks) ----
        const int NPB = 136;
        int pb = blockIdx.x - 8;
        const float4* W4 = (const float4*)Wlin;
        const size_t total4 = (size_t)NC * 256 / 4;     // 6.4M float4
        float s = 0.f;
        for (size_t i = (size_t)pb * 512 + tid; i < total4; i += (size_t)NPB * 512) {
            float4 v = __ldg(&W4[i]);
            s += v.x + v.y + v.z + v.w;
        }
        // keep every warp's loads live (warp-reduce, then lane0 stores)
        s += __shfl_xor_sync(0xFFFFFFFFu, s, 16);
        s += __shfl_xor_sync(0xFFFFFFFFu, s, 8);
        s += __shfl_xor_sync(0xFFFFFFFFu, s, 4);
        s += __shfl_xor_sync(0xFFFFFFFFu, s, 2);
        s += __shfl_xor_sync(0xFFFFFFFFu, s, 1);
        if ((tid & 31) == 0) g_sink[blockIdx.x * 16 + (tid >> 5)] = s;
        return;
    }

    // ---- recurrence cluster (blocks 0..7) ----
    uint32_t rank; asm("mov.u32 %0, %%cluster_ctarank;" : "=r"(rank));
    int cb   = rank * CPB;
    int lr   = tid >> 2;                 // local row 0..127
    int seg  = tid & 3;                  // k-quarter
    int grow = (lr >> 5) * 256 + cb + (lr & 31);   // global gate row

    __shared__ __align__(16) float hbuf[2][2 * H]; // double-buffered full h vector
    __shared__ float gates[128];
    __shared__ float csh[CPB];
    __shared__ float xgl_sh[SEQ][128];   // staged x-gates, indexed by local row

    const float4* wr = (const float4*)(Whh_l + grow * 256 + seg * 64);
    u64 wreg[32];
#pragma unroll
    for (int i = 0; i < 16; i++) {
        float4 w = __ldg(&wr[i]);
        wreg[2 * i]     = pk(w.x, w.y);
        wreg[2 * i + 1] = pk(w.z, w.w);
    }
    // stage x-gates: xgl_sh[t][l] = g_xgl[t][grow(l)]
    for (int idx = tid; idx < SEQ * 128; idx += 512) {
        int t = idx >> 7, l = idx & 127;
        int gl = (l >> 5) * 256 + cb + (l & 31);
        xgl_sh[t][l] = g_xgl[t][gl];
    }
    if (tid < 2 * H) hbuf[0][tid] = h0l[tid];
    if (tid < CPB)   csh[tid] = c0l[cb + tid];
    __syncthreads();

    for (int t = 0; t < SEQ; t++) {
        int rb = t & 1, wb = rb ^ 1;
        const float4* hp4 = (const float4*)(&hbuf[rb][seg * 64]);
        u64 acc0 = 0ull, acc1 = 0ull;
#pragma unroll
        for (int i = 0; i < 16; i++) {
            float4 h4 = hp4[i];              // LDS, ~29cyc
            acc0 = fma2(wreg[2 * i],     pk(h4.x, h4.y), acc0);
            acc1 = fma2(wreg[2 * i + 1], pk(h4.z, h4.w), acc1);
        }
        float2 a = unpk(acc0), b = unpk(acc1);
        float s = a.x + a.y + b.x + b.y;
        s += __shfl_xor_sync(0xFFFFFFFFu, s, 1);
        s += __shfl_xor_sync(0xFFFFFFFFu, s, 2);
        if (seg == 0) gates[lr] = s + xgl_sh[t][lr];
        __syncthreads();
        if (tid < CPB) {
            float gi = gates[tid],           gf = gates[CPB + tid];
            float gg = gates[2 * CPB + tid], go = gates[3 * CPB + tid];
            float c2 = sigf(gf) * csh[tid] + sigf(gi) * tanhfast(gg);
            float h2 = sigf(go) * tanhfast(c2);
            csh[tid] = c2;
            g_hl[t][cb + tid] = h2;          // for k_gemm (visible at kernel end)
            // broadcast h2 into every cluster CTA's write buffer
            uint32_t loff = smem_u32(&hbuf[wb][cb + tid]);
#pragma unroll
            for (int rt = 0; rt < 8; rt++) {
                uint32_t raddr;
                asm("mapa.shared::cluster.u32 %0, %1, %2;" : "=r"(raddr) : "r"(loff), "r"(rt));
                asm volatile("st.shared::cluster.f32 [%0], %1;" :: "r"(raddr), "f"(h2));
            }
        }
        // cluster barrier: arrive(release) orders the DSMEM stores,
        // wait(acquire) makes them visible. Also serves as block barrier.
        asm volatile("barrier.cluster.arrive.aligned;" ::: "memory");
        asm volatile("barrier.cluster.wait.aligned;"   ::: "memory");
    }
}

// =====================================================================
// K4: out[t][n] = hl[t] . Wlin[n] + blin[n]   (20 x 100000)
// Wlin is L2-resident after the k_l prewarm -> LTS-bound, not DRAM-bound.
// Lane map: rr=lane%4 (row), ks=lane/4 (k-eighth) -> every LDG.128 covers
// 4 full 128B lines. 2 rows/thread, 8 warps x 8 rows = 64 rows/block.
// Software-pipelined: iteration c+1's weight loads issue before c's FMAs.
// =====================================================================
__global__ void __launch_bounds__(256)
k_gemm(const float* __restrict__ Wlin, const float* __restrict__ blin,
       float* __restrict__ out)
{
    __shared__ __align__(16) float2 fbp[10][256];   // fbp[tp][k] = (hl[2tp][k], hl[2tp+1][k])
    int tid = threadIdx.x;
#pragma unroll
    for (int i = 0; i < 10; i++) {
        int idx = i * 256 + tid;
        int tp = idx >> 8, k = idx & 255;
        fbp[tp][k] = make_float2(g_hl[2 * tp][k], g_hl[2 * tp + 1][k]);
    }
    __syncthreads();

    int warp = tid >> 5, lane = tid & 31;
    int rr = lane & 3, ks = lane >> 2;
    int rbase = blockIdx.x * 64 + warp * 8 + rr;
    int r0c = (rbase < NC)     ? rbase     : NC - 1;
    int r1c = (rbase + 4 < NC) ? rbase + 4 : NC - 1;
    const float4* wp0 = (const float4*)(Wlin + (size_t)r0c * 256 + ks * 4);
    const float4* wp1 = (const float4*)(Wlin + (size_t)r1c * 256 + ks * 4);

    u64 acc[2][10];
#pragma unroll
    for (int g = 0; g < 2; g++)
#pragma unroll
        for (int tp = 0; tp < 10; tp++) acc[g][tp] = 0ull;

    float4 wc[2], wn[2];
    wc[0] = __ldg(wp0); wc[1] = __ldg(wp1);
    wn[0] = wc[0];      wn[1] = wc[1];

#pragma unroll
    for (int c = 0; c < 8; c++) {
        if (c < 7) {                       // prefetch next k-chunk (overlaps FMAs below)
            wn[0] = __ldg(wp0 + (c + 1) * 8);
            wn[1] = __ldg(wp1 + (c + 1) * 8);
        }
        int k0 = c * 32 + ks * 4;
        u64 ws[2][4];
#pragma unroll
        for (int g = 0; g < 2; g++) {
            ws[g][0] = pk(wc[g].x, wc[g].x); ws[g][1] = pk(wc[g].y, wc[g].y);
            ws[g][2] = pk(wc[g].z, wc[g].z); ws[g][3] = pk(wc[g].w, wc[g].w);
        }
#pragma unroll
        for (int tp = 0; tp < 10; tp++) {
            ulonglong2 f01 = *(const ulonglong2*)&fbp[tp][k0];
            ulonglong2 f23 = *(const ulonglong2*)&fbp[tp][k0 + 2];
#pragma unroll
            for (int g = 0; g < 2; g++) {
                acc[g][tp] = fma2(ws[g][0], f01.x, acc[g][tp]);
                acc[g][tp] = fma2(ws[g][1], f01.y, acc[g][tp]);
                acc[g][tp] = fma2(ws[g][2], f23.x, acc[g][tp]);
                acc[g][tp] = fma2(ws[g][3], f23.y, acc[g][tp]);
            }
        }
        wc[0] = wn[0]; wc[1] = wn[1];
    }

    // reduce across the 8 k-eighth lanes (xor 4,8,16), then write
#pragma unroll
    for (int g = 0; g < 2; g++) {
        int r = rbase + g * 4;
        float bv = (r < NC) ? __ldg(&blin[r]) : 0.f;
#pragma unroll
        for (int tp = 0; tp < 10; tp++) {
            float2 v = unpk(acc[g][tp]);
#pragma unroll
            for (int off = 4; off <= 16; off <<= 1) {
                v.x += __shfl_xor_sync(0xFFFFFFFFu, v.x, off);
                v.y += __shfl_xor_sync(0xFFFFFFFFu, v.y, off);
            }
            if (ks == 0 && r < NC) {
                out[(size_t)(2 * tp) * NC + r]     = v.x + bv;
                out[(size_t)(2 * tp + 1) * NC + r] = v.y + bv;
            }
        }
    }
}

// =====================================================================
extern "C" void kernel_launch(void* const* d_in, const int* in_sizes, int n_in,
                              void* d_out, int out_size)
{
    const float* x     = (const float*)d_in[0];
    const float* h0f   = (const float*)d_in[1];
    const float* c0f   = (const float*)d_in[2];
    const float* h0b   = (const float*)d_in[3];
    const float* c0b   = (const float*)d_in[4];
    const float* h0l   = (const float*)d_in[5];
    const float* c0l   = (const float*)d_in[6];
    const float* Wih_f = (const float*)d_in[7];
    const float* Whh_f = (const float*)d_in[8];
    const float* bih_f = (const float*)d_in[9];
    const float* bhh_f = (const float*)d_in[10];
    const float* Wih_b = (const float*)d_in[11];
    const float* Whh_b = (const float*)d_in[12];
    const float* bih_b = (const float*)d_in[13];
    const float* bhh_b = (const float*)d_in[14];
    const float* Wih_l = (const float*)d_in[15];
    const float* Whh_l = (const float*)d_in[16];
    const float* bih_l = (const float*)d_in[17];
    const float* bhh_l = (const float*)d_in[18];
    const float* Wlin  = (const float*)d_in[19];
    const float* blin  = (const float*)d_in[20];
    float* out = (float*)d_out;

    cudaFuncSetAttribute(k_fb, cudaFuncAttributeMaxDynamicSharedMemorySize, FB_SMEM);

    k_pre<<<2 * SEQ, 512>>>(x, Wih_f, bih_f, bhh_f, Wih_b, bih_b, bhh_b);
    k_fb<<<2, 512, FB_SMEM>>>(Whh_f, Whh_b, h0f, c0f, h0b, c0b);
    k_lpre<<<SEQ * 4, 256>>>(Wih_l, bih_l, bhh_l);
    k_l<<<144, 512>>>(Whh_l, h0l, c0l, Wlin);
    k_gemm<<<(NC + 63) / 64, 256>>>(Wlin, blin, out);
}

// round 9
// speedup vs baseline: 1.1677x; 1.0261x over previous
#include <cuda_runtime.h>
#include <math.h>
#include <stdint.h>

#define SEQ 20
#define H   128
#define NC  100000

typedef unsigned long long u64;

// ---------------- device scratch (no allocations allowed) ----------------
__device__ float g_xg[2][SEQ][4 * H];    // fwd/bwd gate pre-activations from x (+both biases)
__device__ float g_hseq[2][SEQ][H];      // fwd/bwd hidden outputs (bwd kept in scan order)
__device__ float g_xgl[SEQ][8 * H];      // combined-LSTM gate pre-activations from comb input
__device__ float g_hl[SEQ][2 * H];       // combined-LSTM hidden outputs

// ---------------- f32x2 helpers ----------------
__device__ __forceinline__ u64 pk(float a, float b) {
    u64 r; asm("mov.b64 %0, {%1, %2};" : "=l"(r) : "f"(a), "f"(b)); return r;
}
__device__ __forceinline__ u64 fma2(u64 a, u64 b, u64 c) {
    u64 d; asm("fma.rn.f32x2 %0, %1, %2, %3;" : "=l"(d) : "l"(a), "l"(b), "l"(c)); return d;
}
__device__ __forceinline__ float2 unpk(u64 v) {
    float a, b; asm("mov.b64 {%0, %1}, %2;" : "=f"(a), "=f"(b) : "l"(v));
    return make_float2(a, b);
}
// fast activations: MUFU-based, err ~1e-6 (tolerance is 1e-3; measured 3.9e-7)
__device__ __forceinline__ float sigf(float x) {
    return __fdividef(1.0f, 1.0f + __expf(-x));
}
__device__ __forceinline__ float tanhfast(float x) {
    float e = __expf(-2.0f * fabsf(x));            // in (0,1]; no overflow
    float r = __fdividef(1.0f - e, 1.0f + e);
    return copysignf(r, x);
}

__device__ __forceinline__ uint32_t smem_u32(const void* p) {
    uint32_t a;
    asm("{ .reg .u64 t; cvta.to.shared.u64 t, %1; cvt.u32.u64 %0, t; }" : "=r"(a) : "l"(p));
    return a;
}

// =====================================================================
// K0: x-projections for fwd/bwd LSTMs.
// grid = 40 blocks (dir*20+t), 512 threads (one gate row each).
// =====================================================================
__global__ void k_pre(const float* __restrict__ x,
                      const float* __restrict__ Wih_f, const float* __restrict__ bih_f,
                      const float* __restrict__ bhh_f,
                      const float* __restrict__ Wih_b, const float* __restrict__ bih_b,
                      const float* __restrict__ bhh_b)
{
    int bx  = blockIdx.x;
    int dir = bx / SEQ;
    int t   = bx % SEQ;
    int r   = threadIdx.x;              // 0..511 gate row

    __shared__ float4 xs[H / 4];
    if (r < H / 4)
        xs[r] = ((const float4*)(x + (dir ? (SEQ - 1 - t) : t) * H))[r];
    __syncthreads();

    const float* Wih = dir ? Wih_b : Wih_f;
    const float4* wr = (const float4*)(Wih + r * H);
    float acc = 0.f;
#pragma unroll
    for (int i = 0; i < H / 4; i++) {
        float4 w = __ldg(&wr[i]);
        float4 xv = xs[i];
        acc += w.x * xv.x + w.y * xv.y + w.z * xv.z + w.w * xv.w;
    }
    const float* bi = dir ? bih_b : bih_f;
    const float* bh = dir ? bhh_b : bhh_f;
    g_xg[dir][t][r] = acc + bi[r] + bh[r];
}

// =====================================================================
// K1: fwd + bwd recurrences. One block per direction, no inter-block sync.
// 512 threads, one gate row each. Whh row: cols 0..63 in registers (f32x2),
// cols 64..127 in 128KB shared (row-minor -> conflict-free).
// x-gate pre-activations for all 20 steps staged into smem at entry.
// =====================================================================
#define FB_WSH_BYTES (16 * 512 * 16)
#define FB_XG_BYTES  (SEQ * 512 * 4)
#define FB_SMEM (FB_WSH_BYTES + FB_XG_BYTES + 64 * 8 + 512 * 4 + 128 * 4)

__global__ void __launch_bounds__(512)
k_fb(const float* __restrict__ Whh_f, const float* __restrict__ Whh_b,
     const float* __restrict__ h0f, const float* __restrict__ c0f,
     const float* __restrict__ h0b, const float* __restrict__ c0b)
{
    extern __shared__ __align__(16) char smem[];
    ulonglong2* wsh  = (ulonglong2*)smem;                          // [16][512] (cols 64..127)
    float*      xgsh = (float*)(smem + FB_WSH_BYTES);              // [SEQ][512]
    u64*        hsh  = (u64*)(smem + FB_WSH_BYTES + FB_XG_BYTES);  // [64] packed h pairs
    float*      gates = (float*)(smem + FB_WSH_BYTES + FB_XG_BYTES + 64 * 8);  // [512]
    float*      csh  = gates + 512;                                // [128]

    int dir = blockIdx.x;
    int r   = threadIdx.x;
    const float* Whh = dir ? Whh_b : Whh_f;
    const float* h0  = dir ? h0b : h0f;
    const float* c0  = dir ? c0b : c0f;

    const float4* wr = (const float4*)(Whh + r * H);
    u64 wreg[32];
#pragma unroll
    for (int i = 0; i < 16; i++) {                 // cols 0..63 -> registers
        float4 w = __ldg(&wr[i]);
        wreg[2 * i]     = pk(w.x, w.y);
        wreg[2 * i + 1] = pk(w.z, w.w);
    }
#pragma unroll
    for (int m = 0; m < 16; m++) {                 // cols 64..127 -> shared
        float4 w = __ldg(&wr[16 + m]);
        wsh[m * 512 + r] = make_ulonglong2(pk(w.x, w.y), pk(w.z, w.w));
    }
#pragma unroll
    for (int t = 0; t < SEQ; t++)                  // stage x-gates (coalesced, parallel)
        xgsh[t * 512 + r] = g_xg[dir][t][r];
    if (r < 64) hsh[r] = pk(h0[2 * r], h0[2 * r + 1]);
    if (r < H)  csh[r] = c0[r];
    __syncthreads();

    const ulonglong2* h2p = (const ulonglong2*)hsh;
    for (int t = 0; t < SEQ; t++) {
        u64 acc0 = 0ull, acc1 = 0ull;
#pragma unroll
        for (int m = 0; m < 16; m++) {             // register-resident half
            ulonglong2 hv = h2p[m];
            acc0 = fma2(wreg[2 * m],     hv.x, acc0);
            acc1 = fma2(wreg[2 * m + 1], hv.y, acc1);
        }
#pragma unroll
        for (int m = 0; m < 16; m++) {             // shared half
            ulonglong2 hv = h2p[16 + m];
            ulonglong2 wv = wsh[m * 512 + r];
            acc0 = fma2(wv.x, hv.x, acc0);
            acc1 = fma2(wv.y, hv.y, acc1);
        }
        float2 a = unpk(acc0), b = unpk(acc1);
        gates[r] = a.x + a.y + b.x + b.y + xgsh[t * 512 + r];
        __syncthreads();
        if (r < H) {
            float gi = gates[r],         gf = gates[H + r];
            float gg = gates[2 * H + r], go = gates[3 * H + r];
            float c2 = sigf(gf) * csh[r] + sigf(gi) * tanhfast(gg);
            float h2 = sigf(go) * tanhfast(c2);
            csh[r] = c2;
            ((float*)hsh)[r] = h2;
            g_hseq[dir][t][r] = h2;
        }
        __syncthreads();
    }
}

// =====================================================================
// K2: combined-LSTM input projections: Wih_l @ concat(fwd,bwd) + biases.
// grid = (20 t) x (4 row-chunks), 256 threads (one of 1024 gate rows each).
// =====================================================================
__global__ void k_lpre(const float* __restrict__ Wih_l,
                       const float* __restrict__ bih_l, const float* __restrict__ bhh_l)
{
    int t     = blockIdx.x >> 2;
    int chunk = blockIdx.x & 3;
    int tid   = threadIdx.x;            // 0..255
    int row   = chunk * 256 + tid;

    __shared__ float cs[2 * H];
    if (tid < H) cs[tid] = g_hseq[0][t][tid];
    else         cs[tid] = g_hseq[1][t][tid - H];
    __syncthreads();

    const float4* wr = (const float4*)(Wih_l + row * 2 * H);
    const float4* cv = (const float4*)cs;
    float acc = 0.f;
#pragma unroll
    for (int i = 0; i < 64; i++) {
        float4 w = __ldg(&wr[i]);
        float4 h = cv[i];
        acc += w.x * h.x + w.y * h.y + w.z * h.z + w.w * h.w;
    }
    g_xgl[t][row] = acc + bih_l[row] + bhh_l[row];
}

// =====================================================================
// K3: combined recurrence (2H=256 cells, Whh_l = 1MB). 8 CTAs in ONE
// CLUSTER (grid=8), 32 cells each; weights register-resident; h vector in
// per-CTA smem (double-buffered), broadcast to all 8 CTAs via
// st.shared::cluster; per-step sync = barrier.cluster (release/acquire).
// Prewarm removed: measured to cost ~55us in k_l while buying k_gemm
// only ~0.7us (k_gemm is issue-bound, not DRAM-bound).
// =====================================================================
__global__ void __launch_bounds__(512) __cluster_dims__(8, 1, 1)
k_l(const float* __restrict__ Whh_l,
    const float* __restrict__ h0l, const float* __restrict__ c0l)
{
    const int CPB = 32;
    int tid  = threadIdx.x;
    uint32_t rank; asm("mov.u32 %0, %%cluster_ctarank;" : "=r"(rank));
    int cb   = rank * CPB;
    int lr   = tid >> 2;                 // local row 0..127
    int seg  = tid & 3;                  // k-quarter
    int grow = (lr >> 5) * 256 + cb + (lr & 31);   // global gate row

    __shared__ __align__(16) float hbuf[2][2 * H]; // double-buffered full h vector
    __shared__ float gates[128];
    __shared__ float csh[CPB];
    __shared__ float xgl_sh[SEQ][128];   // staged x-gates, indexed by local row

    const float4* wr = (const float4*)(Whh_l + grow * 256 + seg * 64);
    u64 wreg[32];
#pragma unroll
    for (int i = 0; i < 16; i++) {
        float4 w = __ldg(&wr[i]);
        wreg[2 * i]     = pk(w.x, w.y);
        wreg[2 * i + 1] = pk(w.z, w.w);
    }
    // stage x-gates: xgl_sh[t][l] = g_xgl[t][grow(l)]
    for (int idx = tid; idx < SEQ * 128; idx += 512) {
        int t = idx >> 7, l = idx & 127;
        int gl = (l >> 5) * 256 + cb + (l & 31);
        xgl_sh[t][l] = g_xgl[t][gl];
    }
    if (tid < 2 * H) hbuf[0][tid] = h0l[tid];
    if (tid < CPB)   csh[tid] = c0l[cb + tid];
    __syncthreads();

    for (int t = 0; t < SEQ; t++) {
        int rb = t & 1, wb = rb ^ 1;
        const float4* hp4 = (const float4*)(&hbuf[rb][seg * 64]);
        u64 acc0 = 0ull, acc1 = 0ull;
#pragma unroll
        for (int i = 0; i < 16; i++) {
            float4 h4 = hp4[i];              // LDS, ~29cyc
            acc0 = fma2(wreg[2 * i],     pk(h4.x, h4.y), acc0);
            acc1 = fma2(wreg[2 * i + 1], pk(h4.z, h4.w), acc1);
        }
        float2 a = unpk(acc0), b = unpk(acc1);
        float s = a.x + a.y + b.x + b.y;
        s += __shfl_xor_sync(0xFFFFFFFFu, s, 1);
        s += __shfl_xor_sync(0xFFFFFFFFu, s, 2);
        if (seg == 0) gates[lr] = s + xgl_sh[t][lr];
        __syncthreads();
        if (tid < CPB) {
            float gi = gates[tid],           gf = gates[CPB + tid];
            float gg = gates[2 * CPB + tid], go = gates[3 * CPB + tid];
            float c2 = sigf(gf) * csh[tid] + sigf(gi) * tanhfast(gg);
            float h2 = sigf(go) * tanhfast(c2);
            csh[tid] = c2;
            g_hl[t][cb + tid] = h2;          // for k_gemm (visible at kernel end)
            // broadcast h2 into every cluster CTA's write buffer
            uint32_t loff = smem_u32(&hbuf[wb][cb + tid]);
#pragma unroll
            for (int rt = 0; rt < 8; rt++) {
                uint32_t raddr;
                asm("mapa.shared::cluster.u32 %0, %1, %2;" : "=r"(raddr) : "r"(loff), "r"(rt));
                asm volatile("st.shared::cluster.f32 [%0], %1;" :: "r"(raddr), "f"(h2));
            }
        }
        // cluster barrier: arrive(release) orders the DSMEM stores,
        // wait(acquire) makes them visible. Also serves as block barrier.
        asm volatile("barrier.cluster.arrive.aligned;" ::: "memory");
        asm volatile("barrier.cluster.wait.aligned;"   ::: "memory");
    }
}

// =====================================================================
// K4: out[t][n] = hl[t] . Wlin[n] + blin[n]   (20 x 100000)
// Issue-floor ~15us (8M warp-fma2) == DRAM floor ~13us (102MB).
// __launch_bounds__(256,2): guarantee 2 CTA/SM (no spills/1-CTA collapse).
// Prefetch depth 2: 320 cyc of FMA issue covers 577-cyc DRAM latency
// together with the co-resident CTA.
// Lane map: rr=lane%4 (row), ks=lane/4 (k-eighth) -> every LDG.128 covers
// 4 full 128B lines; fbp LDS broadcasts dedup to 128B/warp-instr.
// =====================================================================
__global__ void __launch_bounds__(256, 2)
k_gemm(const float* __restrict__ Wlin, const float* __restrict__ blin,
       float* __restrict__ out)
{
    __shared__ __align__(16) float2 fbp[10][256];   // fbp[tp][k] = (hl[2tp][k], hl[2tp+1][k])
    int tid = threadIdx.x;
#pragma unroll
    for (int i = 0; i < 10; i++) {
        int idx = i * 256 + tid;
        int tp = idx >> 8, k = idx & 255;
        fbp[tp][k] = make_float2(g_hl[2 * tp][k], g_hl[2 * tp + 1][k]);
    }
    __syncthreads();

    int warp = tid >> 5, lane = tid & 31;
    int rr = lane & 3, ks = lane >> 2;
    int rbase = blockIdx.x * 64 + warp * 8 + rr;
    int r0c = (rbase < NC)     ? rbase     : NC - 1;
    int r1c = (rbase + 4 < NC) ? rbase + 4 : NC - 1;
    const float4* wp0 = (const float4*)(Wlin + (size_t)r0c * 256 + ks * 4);
    const float4* wp1 = (const float4*)(Wlin + (size_t)r1c * 256 + ks * 4);

    u64 acc[2][10];
#pragma unroll
    for (int g = 0; g < 2; g++)
#pragma unroll
        for (int tp = 0; tp < 10; tp++) acc[g][tp] = 0ull;

    // triple-buffered weights: chunk c (wa), c+1 (wb), c+2 loading (wn)
    float4 wa[2], wb[2], wn[2];
    wa[0] = __ldg(wp0);     wa[1] = __ldg(wp1);
    wb[0] = __ldg(wp0 + 8); wb[1] = __ldg(wp1 + 8);
    wn[0] = wa[0];          wn[1] = wa[1];

#pragma unroll
    for (int c = 0; c < 8; c++) {
        if (c < 6) {                       // prefetch chunk c+2 (2-deep pipeline)
            wn[0] = __ldg(wp0 + (c + 2) * 8);
            wn[1] = __ldg(wp1 + (c + 2) * 8);
        }
        int k0 = c * 32 + ks * 4;
        u64 ws[2][4];
#pragma unroll
        for (int g = 0; g < 2; g++) {
            ws[g][0] = pk(wa[g].x, wa[g].x); ws[g][1] = pk(wa[g].y, wa[g].y);
            ws[g][2] = pk(wa[g].z, wa[g].z); ws[g][3] = pk(wa[g].w, wa[g].w);
        }
#pragma unroll
        for (int tp = 0; tp < 10; tp++) {
            ulonglong2 f01 = *(const ulonglong2*)&fbp[tp][k0];
            ulonglong2 f23 = *(const ulonglong2*)&fbp[tp][k0 + 2];
#pragma unroll
            for (int g = 0; g < 2; g++) {
                acc[g][tp] = fma2(ws[g][0], f01.x, acc[g][tp]);
                acc[g][tp] = fma2(ws[g][1], f01.y, acc[g][tp]);
                acc[g][tp] = fma2(ws[g][2], f23.x, acc[g][tp]);
                acc[g][tp] = fma2(ws[g][3], f23.y, acc[g][tp]);
            }
        }
        wa[0] = wb[0]; wa[1] = wb[1];
        wb[0] = wn[0]; wb[1] = wn[1];
    }

    // reduce across the 8 k-eighth lanes (xor 4,8,16), then write
#pragma unroll
    for (int g = 0; g < 2; g++) {
        int r = rbase + g * 4;
        float bv = (r < NC) ? __ldg(&blin[r]) : 0.f;
#pragma unroll
        for (int tp = 0; tp < 10; tp++) {
            float2 v = unpk(acc[g][tp]);
#pragma unroll
            for (int off = 4; off <= 16; off <<= 1) {
                v.x += __shfl_xor_sync(0xFFFFFFFFu, v.x, off);
                v.y += __shfl_xor_sync(0xFFFFFFFFu, v.y, off);
            }
            if (ks == 0 && r < NC) {
                out[(size_t)(2 * tp) * NC + r]     = v.x + bv;
                out[(size_t)(2 * tp + 1) * NC + r] = v.y + bv;
            }
        }
    }
}

// =====================================================================
extern "C" void kernel_launch(void* const* d_in, const int* in_sizes, int n_in,
                              void* d_out, int out_size)
{
    const float* x     = (const float*)d_in[0];
    const float* h0f   = (const float*)d_in[1];
    const float* c0f   = (const float*)d_in[2];
    const float* h0b   = (const float*)d_in[3];
    const float* c0b   = (const float*)d_in[4];
    const float* h0l   = (const float*)d_in[5];
    const float* c0l   = (const float*)d_in[6];
    const float* Wih_f = (const float*)d_in[7];
    const float* Whh_f = (const float*)d_in[8];
    const float* bih_f = (const float*)d_in[9];
    const float* bhh_f = (const float*)d_in[10];
    const float* Wih_b = (const float*)d_in[11];
    const float* Whh_b = (const float*)d_in[12];
    const float* bih_b = (const float*)d_in[13];
    const float* bhh_b = (const float*)d_in[14];
    const float* Wih_l = (const float*)d_in[15];
    const float* Whh_l = (const float*)d_in[16];
    const float* bih_l = (const float*)d_in[17];
    const float* bhh_l = (const float*)d_in[18];
    const float* Wlin  = (const float*)d_in[19];
    const float* blin  = (const float*)d_in[20];
    float* out = (float*)d_out;

    cudaFuncSetAttribute(k_fb, cudaFuncAttributeMaxDynamicSharedMemorySize, FB_SMEM);

    k_pre<<<2 * SEQ, 512>>>(x, Wih_f, bih_f, bhh_f, Wih_b, bih_b, bhh_b);
    k_fb<<<2, 512, FB_SMEM>>>(Whh_f, Whh_b, h0f, c0f, h0b, c0b);
    k_lpre<<<SEQ * 4, 256>>>(Wih_l, bih_l, bhh_l);
    k_l<<<8, 512>>>(Whh_l, h0l, c0l);
    k_gemm<<<(NC + 63) / 64, 256>>>(Wlin, blin, out);
}